// round 15
// baseline (speedup 1.0000x reference)
#include <cuda_runtime.h>
#include <math.h>

#define Bn   32
#define Sn   128
#define Hn   768
#define Ln   12
#define NHn  12
#define DHn  64
#define FFn  3072
#define Tn   9
#define SPn  127
#define MTOK (Bn*Sn)          // 4096 tokens

// conv geometry
#define C1OUT 382
#define C2OUT 189
#define K1    635             // 127*5
#define K2    381             // 127*3

// ---------------- scratch (device globals; no allocations) ----------------
__device__ float g_h   [MTOK * Hn];
__device__ float g_qkv [MTOK * 3 * Hn];
__device__ float g_att [MTOK * Hn];
__device__ float g_ff  [MTOK * FFn];
__device__ float g_p1  [Bn * K1 * C1OUT];
__device__ float g_c1  [Bn * SPn * C1OUT];
__device__ float g_p2  [Bn * K2 * C2OUT];
__device__ float g_c2  [Bn * SPn * C2OUT];
__device__ float g_lg  [Bn * SPn * Tn];
__device__ float g_llhb[Bn];

// =====================================================================
// TF32x3 tensor-core GEMM, cp.async double-buffered.
//   C = A(MxK) @ B(KxN) + bias(N), optional exact GELU.
// REQUIRES: M,N % 128 == 0, K % 32 == 0 (no bounds checks).
// Raw fp32 tiles live in smem once; hi/lo tf32 split happens at
// fragment-load time. product = Ahi*Bhi + Alo*Bhi + Ahi*Blo.
// 128x128 block tile, KTILE=32, 8 warps (2m x 4n) of 64x32 warp tiles.
// Conflict-free fragment LDS:
//   As[m][36]  -> bank(4g+t4) lane-unique
//   Bs[k][136] -> bank(8t4+g) lane-unique
// Dyn smem: 2 * (128*36 + 32*136) * 4 = 71680 B (two k-tile buffers).
// =====================================================================
#define AS_ELE (128 * 36)
#define BS_ELE (32 * 136)
#define BUF_ELE (AS_ELE + BS_ELE)
#define GEMM_SMEM (2 * BUF_ELE * 4)

__device__ __forceinline__ float to_tf32(float x) {
    float r;
    asm("cvt.rna.tf32.f32 %0, %1;" : "=f"(r) : "f"(x));
    return r;
}

__device__ __forceinline__ unsigned sptr(const void* p) {
    return (unsigned)__cvta_generic_to_shared(p);
}

#define CP16(dst, src) \
    asm volatile("cp.async.cg.shared.global [%0], [%1], 16;" :: "r"(dst), "l"(src))
#define CP_COMMIT() asm volatile("cp.async.commit_group;")
#define CP_WAIT1()  asm volatile("cp.async.wait_group 1;")
#define CP_WAIT0()  asm volatile("cp.async.wait_group 0;")

__device__ __forceinline__ void mma_tf32(float* c, const unsigned* a, const unsigned* b) {
    asm volatile(
        "mma.sync.aligned.m16n8k8.row.col.f32.tf32.tf32.f32 "
        "{%0,%1,%2,%3}, {%4,%5,%6,%7}, {%8,%9}, {%0,%1,%2,%3};"
        : "+f"(c[0]), "+f"(c[1]), "+f"(c[2]), "+f"(c[3])
        : "r"(a[0]), "r"(a[1]), "r"(a[2]), "r"(a[3]), "r"(b[0]), "r"(b[1]));
}

__global__ __launch_bounds__(256)
void tf32x3_gemm_kernel(const float* __restrict__ A, const float* __restrict__ B,
                        const float* __restrict__ bias, float* __restrict__ C,
                        int M, int N, int K, int gelu_flag)
{
    extern __shared__ float dyn[];

    const int tid  = threadIdx.x;
    const int wid  = tid >> 5;
    const int lane = tid & 31;
    const int g    = lane >> 2;         // 0..7
    const int t4   = lane & 3;          // 0..3
    const int wm   = (wid >> 2) * 64;   // warp m offset (0 / 64)
    const int wn   = (wid & 3) * 32;    // warp n offset (0/32/64/96)
    const long m0  = (long)blockIdx.y * 128;
    const long n0  = (long)blockIdx.x * 128;

    // loader indices
    const int lm  = tid >> 1;           // A row 0..127
    const int lkh = (tid & 1) * 16;     // A k half (0/16)
    const int bk  = tid >> 3;           // B k row 0..31
    const int bn4 = (tid & 7) * 16;     // B n chunk (16 floats)

    const float* Ag = A + (m0 + lm) * K + lkh;
    const float* Bg = B + (long)bk * N + n0 + bn4;
    const long  BgK = (long)32 * N;     // per-ktile B advance

    // smem buffer bases (bytes for cp.async dst)
    unsigned sa_base[2], sb_base[2];
    float*   As_f[2];
    float*   Bs_f[2];
#pragma unroll
    for (int b2 = 0; b2 < 2; b2++) {
        As_f[b2] = dyn + b2 * BUF_ELE;
        Bs_f[b2] = dyn + b2 * BUF_ELE + AS_ELE;
        sa_base[b2] = sptr(&As_f[b2][lm * 36 + lkh]);
        sb_base[b2] = sptr(&Bs_f[b2][bk * 136 + bn4]);
    }

    float acc[4][4][4];
#pragma unroll
    for (int mt = 0; mt < 4; mt++)
#pragma unroll
        for (int nt = 0; nt < 4; nt++)
#pragma unroll
            for (int r = 0; r < 4; r++) acc[mt][nt][r] = 0.f;

    const int NT = K >> 5;

    // prologue: stage tile 0 into buffer 0
    {
        const float* ga = Ag;
        const float* gb = Bg;
#pragma unroll
        for (int i = 0; i < 4; i++) CP16(sa_base[0] + 16 * i, ga + 4 * i);
#pragma unroll
        for (int i = 0; i < 4; i++) CP16(sb_base[0] + 16 * i, gb + 4 * i);
        CP_COMMIT();
    }

    for (int kt = 0; kt < NT; kt++) {
        const int buf = kt & 1;
        if (kt + 1 < NT) {
            const int nb = buf ^ 1;
            const float* ga = Ag + (kt + 1) * 32;
            const float* gb = Bg + (long)(kt + 1) * BgK;
#pragma unroll
            for (int i = 0; i < 4; i++) CP16(sa_base[nb] + 16 * i, ga + 4 * i);
#pragma unroll
            for (int i = 0; i < 4; i++) CP16(sb_base[nb] + 16 * i, gb + 4 * i);
            CP_COMMIT();
            CP_WAIT1();
        } else {
            CP_WAIT0();
        }
        __syncthreads();

        const float* Asb = As_f[buf];
        const float* Bsb = Bs_f[buf];

#pragma unroll
        for (int ks = 0; ks < 4; ks++) {
            const int kb = ks * 8;
            unsigned ah[4][4], al[4][4], bh[4][2], bl[4][2];
#pragma unroll
            for (int mt = 0; mt < 4; mt++) {
                const int mr = wm + mt * 16 + g;
                float v0 = Asb[(mr    ) * 36 + kb + t4    ];
                float v1 = Asb[(mr + 8) * 36 + kb + t4    ];
                float v2 = Asb[(mr    ) * 36 + kb + t4 + 4];
                float v3 = Asb[(mr + 8) * 36 + kb + t4 + 4];
                float h0 = to_tf32(v0), h1 = to_tf32(v1);
                float h2 = to_tf32(v2), h3 = to_tf32(v3);
                ah[mt][0] = __float_as_uint(h0); al[mt][0] = __float_as_uint(to_tf32(v0 - h0));
                ah[mt][1] = __float_as_uint(h1); al[mt][1] = __float_as_uint(to_tf32(v1 - h1));
                ah[mt][2] = __float_as_uint(h2); al[mt][2] = __float_as_uint(to_tf32(v2 - h2));
                ah[mt][3] = __float_as_uint(h3); al[mt][3] = __float_as_uint(to_tf32(v3 - h3));
            }
#pragma unroll
            for (int nt = 0; nt < 4; nt++) {
                const int nc = wn + nt * 8 + g;
                float v0 = Bsb[(kb + t4    ) * 136 + nc];
                float v1 = Bsb[(kb + t4 + 4) * 136 + nc];
                float h0 = to_tf32(v0), h1 = to_tf32(v1);
                bh[nt][0] = __float_as_uint(h0); bl[nt][0] = __float_as_uint(to_tf32(v0 - h0));
                bh[nt][1] = __float_as_uint(h1); bl[nt][1] = __float_as_uint(to_tf32(v1 - h1));
            }
#pragma unroll
            for (int mt = 0; mt < 4; mt++)
#pragma unroll
                for (int nt = 0; nt < 4; nt++) {
                    mma_tf32(acc[mt][nt], al[mt], bh[nt]);  // lo*hi
                    mma_tf32(acc[mt][nt], ah[mt], bl[nt]);  // hi*lo
                    mma_tf32(acc[mt][nt], ah[mt], bh[nt]);  // hi*hi
                }
        }
        __syncthreads();
    }

    // epilogue: c0,c1 at (g, 2*t4[,+1]); c2,c3 at (g+8, ...)
#pragma unroll
    for (int mt = 0; mt < 4; mt++) {
#pragma unroll
        for (int nt = 0; nt < 4; nt++) {
            long col = n0 + wn + nt * 8 + 2 * t4;
            float bb0 = bias ? bias[col] : 0.f;
            float bb1 = bias ? bias[col + 1] : 0.f;
#pragma unroll
            for (int half = 0; half < 2; half++) {
                long row = m0 + wm + mt * 16 + g + half * 8;
                float v0 = acc[mt][nt][half * 2 + 0] + bb0;
                float v1 = acc[mt][nt][half * 2 + 1] + bb1;
                if (gelu_flag) {
                    v0 = 0.5f * v0 * (1.f + erff(v0 * 0.70710678118654752f));
                    v1 = 0.5f * v1 * (1.f + erff(v1 * 0.70710678118654752f));
                }
                *(float2*)&C[row * N + col] = make_float2(v0, v1);
            }
        }
    }
}

// =====================================================================
// Generic tiled FFMA SGEMM (small conv GEMMs with odd shapes)
// =====================================================================
__global__ __launch_bounds__(256)
void sgemm_kernel(const float* __restrict__ A, const float* __restrict__ B,
                  const float* __restrict__ bias, float* __restrict__ C,
                  int M, int N, int K,
                  long sA, long sB, long sC, int gelu_flag)
{
    A += (long)blockIdx.z * sA;
    B += (long)blockIdx.z * sB;
    C += (long)blockIdx.z * sC;

    __shared__ float As[8][128];
    __shared__ float Bs[8][128];

    const int tid = threadIdx.x;
    const int ty  = tid >> 4;
    const int tx  = tid & 15;
    const int m0  = blockIdx.y * 128;
    const int n0  = blockIdx.x * 128;

    float acc[8][8];
#pragma unroll
    for (int i = 0; i < 8; i++)
#pragma unroll
        for (int j = 0; j < 8; j++) acc[i][j] = 0.f;

    for (int k0 = 0; k0 < K; k0 += 8) {
#pragma unroll
        for (int u = 0; u < 4; u++) {
            int l = tid * 4 + u;
            int m = l >> 3, k = l & 7;
            int gm = m0 + m, gk = k0 + k;
            As[k][m] = (gm < M && gk < K) ? A[(long)gm * K + gk] : 0.f;
        }
#pragma unroll
        for (int u = 0; u < 4; u++) {
            int l = tid * 4 + u;
            int k = l >> 7, n = l & 127;
            int gk = k0 + k, gn = n0 + n;
            Bs[k][n] = (gk < K && gn < N) ? B[(long)gk * N + gn] : 0.f;
        }
        __syncthreads();
#pragma unroll
        for (int kk = 0; kk < 8; kk++) {
            float a[8], bb[8];
#pragma unroll
            for (int i = 0; i < 8; i++) a[i]  = As[kk][ty * 8 + i];
#pragma unroll
            for (int j = 0; j < 8; j++) bb[j] = Bs[kk][tx * 8 + j];
#pragma unroll
            for (int i = 0; i < 8; i++)
#pragma unroll
                for (int j = 0; j < 8; j++) acc[i][j] += a[i] * bb[j];
        }
        __syncthreads();
    }

#pragma unroll
    for (int i = 0; i < 8; i++) {
        int gm = m0 + ty * 8 + i;
        if (gm >= M) continue;
#pragma unroll
        for (int j = 0; j < 8; j++) {
            int gn = n0 + tx * 8 + j;
            if (gn >= N) continue;
            float v = acc[i][j] + (bias ? bias[gn] : 0.f);
            if (gelu_flag) v = 0.5f * v * (1.f + erff(v * 0.70710678118654752f));
            C[(long)gm * N + gn] = v;
        }
    }
}

// =====================================================================
// Embedding sum
// =====================================================================
__global__ void embed_kernel(const int* __restrict__ ids, const int* __restrict__ tti,
                             const float* __restrict__ tok, const float* __restrict__ pos,
                             const float* __restrict__ typ)
{
    int t = blockIdx.x;
    int s = t & (Sn - 1);
    int id = ids[t], tp = tti[t];
    const float* tr = tok + (long)id * Hn;
    const float* pr = pos + (long)s * Hn;
    const float* yr = typ + (long)tp * Hn;
    for (int i = threadIdx.x; i < Hn; i += blockDim.x)
        g_h[(long)t * Hn + i] = tr[i] + pr[i] + yr[i];
}

// =====================================================================
// LayerNorm: o = LN(a + d) * g + be   (d may be null; o may alias a)
// =====================================================================
__global__ __launch_bounds__(256)
void ln_kernel(const float* __restrict__ a, const float* __restrict__ d,
               const float* __restrict__ g, const float* __restrict__ be,
               float* __restrict__ o)
{
    long t = blockIdx.x;
    const float* ar = a + t * Hn;
    const float* dr = d ? d + t * Hn : nullptr;
    int tid = threadIdx.x;
    float vals[3];
    float sum = 0.f;
#pragma unroll
    for (int j = 0; j < 3; j++) {
        int i = tid + j * 256;
        float v = ar[i] + (dr ? dr[i] : 0.f);
        vals[j] = v; sum += v;
    }
    __shared__ float sh[8];
#pragma unroll
    for (int off = 16; off; off >>= 1) sum += __shfl_xor_sync(0xffffffffu, sum, off);
    if ((tid & 31) == 0) sh[tid >> 5] = sum;
    __syncthreads();
    float tot = 0.f;
#pragma unroll
    for (int w = 0; w < 8; w++) tot += sh[w];
    float mean = tot * (1.f / Hn);
    __syncthreads();
    float sq = 0.f;
#pragma unroll
    for (int j = 0; j < 3; j++) { float c = vals[j] - mean; sq += c * c; }
#pragma unroll
    for (int off = 16; off; off >>= 1) sq += __shfl_xor_sync(0xffffffffu, sq, off);
    if ((tid & 31) == 0) sh[tid >> 5] = sq;
    __syncthreads();
    float vtot = 0.f;
#pragma unroll
    for (int w = 0; w < 8; w++) vtot += sh[w];
    float inv = rsqrtf(vtot * (1.f / Hn) + 1e-12f);
#pragma unroll
    for (int j = 0; j < 3; j++) {
        int i = tid + j * 256;
        o[t * Hn + i] = (vals[j] - mean) * inv * g[i] + be[i];
    }
}

// =====================================================================
// Fused attention per (head, batch)
// =====================================================================
#define ATT_SMEM ((2*64*128 + 128*129) * 4)
__global__ __launch_bounds__(256)
void attention_kernel(const int* __restrict__ am)
{
    int h = blockIdx.x, b = blockIdx.y;
    extern __shared__ float sm[];
    float* Qt = sm;
    float* Kt = sm + 64 * 128;
    float* Ss = sm + 2 * 64 * 128;
    float* Vs = Qt;

    int tid = threadIdx.x;
    const float* base = g_qkv + (long)b * Sn * 3 * Hn + h * DHn;

    for (int idx = tid; idx < Sn * DHn; idx += 256) {
        int s = idx >> 6, d = idx & 63;
        Qt[d * 128 + s] = base[(long)s * 3 * Hn + d];
        Kt[d * 128 + s] = base[(long)s * 3 * Hn + Hn + d];
    }
    __syncthreads();

    int ty = tid >> 4, tx = tid & 15;
    float acc[8][8];
#pragma unroll
    for (int i = 0; i < 8; i++)
#pragma unroll
        for (int j = 0; j < 8; j++) acc[i][j] = 0.f;

    for (int d = 0; d < 64; d++) {
        float a[8], bb[8];
#pragma unroll
        for (int i = 0; i < 8; i++) a[i]  = Qt[d * 128 + ty * 8 + i];
#pragma unroll
        for (int j = 0; j < 8; j++) bb[j] = Kt[d * 128 + tx * 8 + j];
#pragma unroll
        for (int i = 0; i < 8; i++)
#pragma unroll
            for (int j = 0; j < 8; j++) acc[i][j] += a[i] * bb[j];
    }
#pragma unroll
    for (int j = 0; j < 8; j++) {
        int key = tx * 8 + j;
        float bias = (am[b * Sn + key] > 0) ? 0.f : -1e9f;
#pragma unroll
        for (int i = 0; i < 8; i++)
            Ss[(ty * 8 + i) * 129 + key] = acc[i][j] * 0.125f + bias;
    }
    __syncthreads();

    int wid = tid >> 5, lane = tid & 31;
    for (int r = wid; r < 128; r += 8) {
        float mx = -1e30f;
        for (int c = lane; c < 128; c += 32) mx = fmaxf(mx, Ss[r * 129 + c]);
#pragma unroll
        for (int off = 16; off; off >>= 1) mx = fmaxf(mx, __shfl_xor_sync(0xffffffffu, mx, off));
        float sumv = 0.f;
        for (int c = lane; c < 128; c += 32) {
            float e = expf(Ss[r * 129 + c] - mx);
            Ss[r * 129 + c] = e; sumv += e;
        }
#pragma unroll
        for (int off = 16; off; off >>= 1) sumv += __shfl_xor_sync(0xffffffffu, sumv, off);
        float inv = 1.f / sumv;
        for (int c = lane; c < 128; c += 32) Ss[r * 129 + c] *= inv;
    }
    __syncthreads();

    for (int idx = tid; idx < Sn * DHn; idx += 256) {
        int s = idx >> 6, d = idx & 63;
        Vs[s * 64 + d] = base[(long)s * 3 * Hn + 2 * Hn + d];
    }
    __syncthreads();

    float acc2[8][4];
#pragma unroll
    for (int i = 0; i < 8; i++)
#pragma unroll
        for (int j = 0; j < 4; j++) acc2[i][j] = 0.f;

    for (int key = 0; key < 128; key++) {
        float a[8], bb[4];
#pragma unroll
        for (int i = 0; i < 8; i++) a[i]  = Ss[(ty * 8 + i) * 129 + key];
#pragma unroll
        for (int j = 0; j < 4; j++) bb[j] = Vs[key * 64 + tx * 4 + j];
#pragma unroll
        for (int i = 0; i < 8; i++)
#pragma unroll
            for (int j = 0; j < 4; j++) acc2[i][j] += a[i] * bb[j];
    }
    float* outp = g_att + (long)b * Sn * Hn + h * DHn;
#pragma unroll
    for (int i = 0; i < 8; i++)
#pragma unroll
        for (int j = 0; j < 4; j++)
            outp[(long)(ty * 8 + i) * Hn + tx * 4 + j] = acc2[i][j];
}

// =====================================================================
// im2col patches
// =====================================================================
__global__ void patch1_kernel()
{
    long e = (long)blockIdx.x * 256 + threadIdx.x;
    long total = (long)Bn * K1 * C1OUT;
    if (e >= total) return;
    int t  = (int)(e % C1OUT);
    long r = e / C1OUT;
    int ik = (int)(r % K1);
    int b  = (int)(r / K1);
    int i  = ik / 5, k = ik % 5;
    g_p1[e] = g_h[((long)(b * Sn + 1 + i)) * Hn + 2 * t + k];
}

__global__ void patch2_kernel(const float* __restrict__ c1b)
{
    long e = (long)blockIdx.x * 256 + threadIdx.x;
    long total = (long)Bn * K2 * C2OUT;
    if (e >= total) return;
    int t  = (int)(e % C2OUT);
    long r = e / C2OUT;
    int ik = (int)(r % K2);
    int b  = (int)(r / K2);
    int i  = ik / 3, k = ik % 3;
    g_p2[e] = g_c1[((long)b * SPn + i) * C1OUT + 2 * t + 2 * k] + c1b[i];
}

// =====================================================================
// logits
// =====================================================================
__global__ void logits_kernel(const float* __restrict__ c2b,
                              const float* __restrict__ linw,
                              const float* __restrict__ linb)
{
    int e = blockIdx.x * 256 + threadIdx.x;
    if (e >= Bn * SPn * Tn) return;
    int tag = e % Tn;
    int r   = e / Tn;
    int ch  = r % SPn;
    int b   = r / SPn;
    const float* crow = g_c2 + ((long)b * SPn + ch) * C2OUT;
    float cb = c2b[ch];
    float acc = linb[tag];
    for (int t = 0; t < C2OUT; t++)
        acc += (crow[t] + cb) * linw[t * Tn + tag];
    g_lg[e] = acc;
}

// =====================================================================
// CRF
// =====================================================================
__global__ void crf_kernel(const int* __restrict__ am, const int* __restrict__ y,
                           const float* __restrict__ startv, const float* __restrict__ endv,
                           const float* __restrict__ trans, float* __restrict__ dout)
{
    int b = blockIdx.x;
    int j = threadIdx.x;
    const float* em = g_lg + (long)b * SPn * Tn;

    __shared__ float s[Tn], sv[Tn];
    __shared__ int   hist[SPn - 1][Tn];
    __shared__ float tr[Tn * Tn];
    __shared__ int   msk[SPn];
    __shared__ int   pathsh[SPn];

    for (int i = j; i < Tn * Tn; i += 32) tr[i] = trans[i];
    for (int t = j; t < SPn; t += 32) msk[t] = am[b * Sn + 1 + t];
    __syncthreads();

    if (j < Tn) { s[j] = startv[j] + em[j]; sv[j] = s[j]; }
    __syncthreads();

    for (int t = 1; t < SPn; t++) {
        float nsj = 0.f, nvj = 0.f; int bi = 0;
        if (j < Tn) {
            float mx = -1e30f;
#pragma unroll
            for (int i = 0; i < Tn; i++) mx = fmaxf(mx, s[i] + tr[i * Tn + j]);
            float sm = 0.f;
#pragma unroll
            for (int i = 0; i < Tn; i++) sm += expf(s[i] + tr[i * Tn + j] - mx);
            nsj = mx + logf(sm) + em[t * Tn + j];

            float best = -1e30f;
#pragma unroll
            for (int i = 0; i < Tn; i++) {
                float c = sv[i] + tr[i * Tn + j];
                if (c > best) { best = c; bi = i; }
            }
            nvj = best + em[t * Tn + j];
        }
        __syncthreads();
        if (j < Tn) {
            if (msk[t]) { s[j] = nsj; sv[j] = nvj; hist[t - 1][j] = bi; }
            else        { hist[t - 1][j] = j; }
        }
        __syncthreads();
    }

    if (j == 0) {
        float mx = -1e30f;
#pragma unroll
        for (int jj = 0; jj < Tn; jj++) mx = fmaxf(mx, s[jj] + endv[jj]);
        float sm = 0.f;
#pragma unroll
        for (int jj = 0; jj < Tn; jj++) sm += expf(s[jj] + endv[jj] - mx);
        float norm = mx + logf(sm);

        float best = -1e30f; int tag = 0;
#pragma unroll
        for (int jj = 0; jj < Tn; jj++) {
            float c = sv[jj] + endv[jj];
            if (c > best) { best = c; tag = jj; }
        }
        for (int t = SPn - 2; t >= 0; t--) {
            pathsh[t + 1] = tag;
            tag = hist[t][tag];
        }
        pathsh[0] = tag;

        const int* tg = y + b * SPn;
        float sc = startv[tg[0]] + em[tg[0]];
        int cnt = 0;
        for (int t = 0; t < SPn; t++) cnt += msk[t] ? 1 : 0;
        for (int t = 1; t < SPn; t++)
            if (msk[t]) sc += tr[tg[t - 1] * Tn + tg[t]] + em[t * Tn + tg[t]];
        sc += endv[tg[cnt - 1]];
        g_llhb[b] = sc - norm;
    }
    __syncthreads();
    for (int t = j; t < SPn; t += 32)
        dout[1 + b * SPn + t] = (float)pathsh[t];
}

__global__ void finalize_kernel(float* __restrict__ dout)
{
    if (threadIdx.x == 0) {
        float sm = 0.f;
        for (int b = 0; b < Bn; b++) sm += g_llhb[b];
        dout[0] = sm / (float)Bn;
    }
}

// =====================================================================
// host orchestration
// =====================================================================
extern "C" void kernel_launch(void* const* d_in, const int* in_sizes, int n_in,
                              void* d_out, int out_size)
{
    const int*   input_ids = (const int*)  d_in[0];
    const int*   am        = (const int*)  d_in[1];
    const int*   tti       = (const int*)  d_in[2];
    const int*   y_true    = (const int*)  d_in[3];
    const float* tok  = (const float*)d_in[4];
    const float* pos  = (const float*)d_in[5];
    const float* typ  = (const float*)d_in[6];
    const float* eg   = (const float*)d_in[7];
    const float* ebv  = (const float*)d_in[8];
    const float* Wqkv = (const float*)d_in[9];
    const float* bqkv = (const float*)d_in[10];
    const float* Wo   = (const float*)d_in[11];
    const float* bo   = (const float*)d_in[12];
    const float* l1g  = (const float*)d_in[13];
    const float* l1b  = (const float*)d_in[14];
    const float* W1   = (const float*)d_in[15];
    const float* bf1  = (const float*)d_in[16];
    const float* W2   = (const float*)d_in[17];
    const float* bf2  = (const float*)d_in[18];
    const float* l2g  = (const float*)d_in[19];
    const float* l2b  = (const float*)d_in[20];
    const float* c1w  = (const float*)d_in[21];
    const float* c1b  = (const float*)d_in[22];
    const float* c2w  = (const float*)d_in[23];
    const float* c2b  = (const float*)d_in[24];
    const float* linw = (const float*)d_in[25];
    const float* linb = (const float*)d_in[26];
    const float* crs  = (const float*)d_in[27];
    const float* cre  = (const float*)d_in[28];
    const float* crt  = (const float*)d_in[29];
    float* dout = (float*)d_out;

    float *p_h, *p_qkv, *p_att, *p_ff, *p_p1, *p_c1, *p_p2, *p_c2;
    cudaGetSymbolAddress((void**)&p_h,   g_h);
    cudaGetSymbolAddress((void**)&p_qkv, g_qkv);
    cudaGetSymbolAddress((void**)&p_att, g_att);
    cudaGetSymbolAddress((void**)&p_ff,  g_ff);
    cudaGetSymbolAddress((void**)&p_p1,  g_p1);
    cudaGetSymbolAddress((void**)&p_c1,  g_c1);
    cudaGetSymbolAddress((void**)&p_p2,  g_p2);
    cudaGetSymbolAddress((void**)&p_c2,  g_c2);

    cudaFuncSetAttribute(attention_kernel,
                         cudaFuncAttributeMaxDynamicSharedMemorySize, ATT_SMEM);
    cudaFuncSetAttribute(tf32x3_gemm_kernel,
                         cudaFuncAttributeMaxDynamicSharedMemorySize, GEMM_SMEM);

    embed_kernel<<<MTOK, 256>>>(input_ids, tti, tok, pos, typ);
    ln_kernel<<<MTOK, 256>>>(p_h, nullptr, eg, ebv, p_h);

    for (int l = 0; l < Ln; l++) {
        tf32x3_gemm_kernel<<<dim3(18, 32), 256, GEMM_SMEM>>>(
            p_h, Wqkv + (long)l * Hn * 3 * Hn, bqkv + (long)l * 3 * Hn, p_qkv,
            MTOK, 3 * Hn, Hn, 0);
        attention_kernel<<<dim3(NHn, Bn), 256, ATT_SMEM>>>(am);
        tf32x3_gemm_kernel<<<dim3(6, 32), 256, GEMM_SMEM>>>(
            p_att, Wo + (long)l * Hn * Hn, bo + (long)l * Hn, p_qkv,
            MTOK, Hn, Hn, 0);
        ln_kernel<<<MTOK, 256>>>(p_h, p_qkv, l1g + (long)l * Hn, l1b + (long)l * Hn, p_h);
        tf32x3_gemm_kernel<<<dim3(24, 32), 256, GEMM_SMEM>>>(
            p_h, W1 + (long)l * Hn * FFn, bf1 + (long)l * FFn, p_ff,
            MTOK, FFn, Hn, 1);
        tf32x3_gemm_kernel<<<dim3(6, 32), 256, GEMM_SMEM>>>(
            p_ff, W2 + (long)l * FFn * Hn, bf2 + (long)l * Hn, p_qkv,
            MTOK, Hn, FFn, 0);
        ln_kernel<<<MTOK, 256>>>(p_h, p_qkv, l2g + (long)l * Hn, l2b + (long)l * Hn, p_h);
    }

    {
        long t1 = (long)Bn * K1 * C1OUT;
        patch1_kernel<<<(unsigned)((t1 + 255) / 256), 256>>>();
        sgemm_kernel<<<dim3(3, 1, Bn), 256>>>(c1w, p_p1, nullptr, p_c1,
                                              SPn, C1OUT, K1,
                                              0, (long)K1 * C1OUT, (long)SPn * C1OUT, 0);
        long t2 = (long)Bn * K2 * C2OUT;
        patch2_kernel<<<(unsigned)((t2 + 255) / 256), 256>>>(c1b);
        sgemm_kernel<<<dim3(2, 1, Bn), 256>>>(c2w, p_p2, nullptr, p_c2,
                                              SPn, C2OUT, K2,
                                              0, (long)K2 * C2OUT, (long)SPn * C2OUT, 0);
        int t3 = Bn * SPn * Tn;
        logits_kernel<<<(t3 + 255) / 256, 256>>>(c2b, linw, linb);
    }

    crf_kernel<<<Bn, 32>>>(am, y_true, crs, cre, crt, dout);
    finalize_kernel<<<1, 32>>>(dout);
}

// round 16
// speedup vs baseline: 1.1448x; 1.1448x over previous
#include <cuda_runtime.h>
#include <math.h>

#define Bn   32
#define Sn   128
#define Hn   768
#define Ln   12
#define NHn  12
#define DHn  64
#define FFn  3072
#define Tn   9
#define SPn  127
#define MTOK (Bn*Sn)          // 4096 tokens

// conv geometry
#define C1OUT 382
#define C2OUT 189
#define K1    635             // 127*5
#define K2    381             // 127*3

// ---------------- scratch (device globals; no allocations) ----------------
__device__ float g_h   [MTOK * Hn];
__device__ float g_qkv [MTOK * 3 * Hn];
__device__ float g_att [MTOK * Hn];
__device__ float g_ff  [MTOK * FFn];
__device__ float g_p1  [Bn * K1 * C1OUT];
__device__ float g_c1  [Bn * SPn * C1OUT];
__device__ float g_p2  [Bn * K2 * C2OUT];
__device__ float g_c2  [Bn * SPn * C2OUT];
__device__ float g_lg  [Bn * SPn * Tn];
__device__ float g_llhb[Bn];

// =====================================================================
// TF32x3 tensor-core GEMM (split-precision, ~fp32 accuracy) with
// register-staged double buffering of global loads.
//   C = A(MxK) @ B(KxN) + bias(N), optional exact GELU.
// REQUIRES: M,N % 128 == 0, K % 32 == 0.
// hi/lo tf32 split done ONCE at STS time (amortized over fragment reuse);
// product = Alo*Bhi + Ahi*Blo + Ahi*Bhi.
// 128x128 block tile, KTILE=32, 8 warps (2m x 4n) of 64x32 warp tiles.
// Mainloop: STS(tile t) -> sync -> LDG regs(tile t+1) -> MMA(tile t) -> sync.
// LDG latency drains under the MMA phase.
// Conflict-free fragment LDS:
//   As[m][36]  -> bank(4g+t4) lane-unique for (g,t4) A-frag pattern
//   Bs[k][136] -> bank(8t4+g) lane-unique for (t4,g) B-frag pattern
// Dyn smem: (2*128*36 + 2*32*136)*4 = 71680 B (single k-tile, hi+lo).
// =====================================================================
#define GEMM_SMEM ((2*128*36 + 2*32*136) * 4)

__device__ __forceinline__ float to_tf32(float x) {
    float r;
    asm("cvt.rna.tf32.f32 %0, %1;" : "=f"(r) : "f"(x));
    return r;
}

__device__ __forceinline__ void mma_tf32(float* c, const unsigned* a, const unsigned* b) {
    asm volatile(
        "mma.sync.aligned.m16n8k8.row.col.f32.tf32.tf32.f32 "
        "{%0,%1,%2,%3}, {%4,%5,%6,%7}, {%8,%9}, {%0,%1,%2,%3};"
        : "+f"(c[0]), "+f"(c[1]), "+f"(c[2]), "+f"(c[3])
        : "r"(a[0]), "r"(a[1]), "r"(a[2]), "r"(a[3]), "r"(b[0]), "r"(b[1]));
}

__global__ __launch_bounds__(256)
void tf32x3_gemm_kernel(const float* __restrict__ A, const float* __restrict__ B,
                        const float* __restrict__ bias, float* __restrict__ C,
                        int M, int N, int K, int gelu_flag)
{
    extern __shared__ float dyn[];
    float (*As_hi)[36]  = (float(*)[36]) dyn;
    float (*As_lo)[36]  = (float(*)[36])(dyn + 128 * 36);
    float (*Bs_hi)[136] = (float(*)[136])(dyn + 2 * 128 * 36);
    float (*Bs_lo)[136] = (float(*)[136])(dyn + 2 * 128 * 36 + 32 * 136);

    const int tid  = threadIdx.x;
    const int wid  = tid >> 5;
    const int lane = tid & 31;
    const int g    = lane >> 2;         // 0..7
    const int t4   = lane & 3;          // 0..3
    const int wm   = (wid >> 2) * 64;   // warp m offset (0 / 64)
    const int wn   = (wid & 3) * 32;    // warp n offset (0/32/64/96)
    const long m0  = (long)blockIdx.y * 128;
    const long n0  = (long)blockIdx.x * 128;

    // loader indices
    const int lm  = tid >> 1;           // A row 0..127
    const int lkh = (tid & 1) * 16;     // A k half (0/16)
    const int bk  = tid >> 3;           // B k row 0..31
    const int bn4 = (tid & 7) * 16;     // B n chunk (16 floats)

    const float* Ag = A + (m0 + lm) * K + lkh;
    const float* Bg = B + (long)bk * N + n0 + bn4;
    const long  BgK = (long)32 * N;     // per-ktile B advance

    float acc[4][4][4];
#pragma unroll
    for (int mt = 0; mt < 4; mt++)
#pragma unroll
        for (int nt = 0; nt < 4; nt++)
#pragma unroll
            for (int r = 0; r < 4; r++) acc[mt][nt][r] = 0.f;

    const int NT = K >> 5;

    // prefetch tile 0 into registers
    float4 ra[4], rb[4];
#pragma unroll
    for (int i = 0; i < 4; i++) {
        ra[i] = *(const float4*)(Ag + 4 * i);
        rb[i] = *(const float4*)(Bg + 4 * i);
    }

    for (int kt = 0; kt < NT; kt++) {
        // --- split staged registers hi/lo and store to smem (tile kt)
#pragma unroll
        for (int i = 0; i < 4; i++) {
            float4 v = ra[i], h, l;
            h.x = to_tf32(v.x); l.x = to_tf32(v.x - h.x);
            h.y = to_tf32(v.y); l.y = to_tf32(v.y - h.y);
            h.z = to_tf32(v.z); l.z = to_tf32(v.z - h.z);
            h.w = to_tf32(v.w); l.w = to_tf32(v.w - h.w);
            *(float4*)&As_hi[lm][lkh + 4 * i] = h;
            *(float4*)&As_lo[lm][lkh + 4 * i] = l;
            v = rb[i];
            h.x = to_tf32(v.x); l.x = to_tf32(v.x - h.x);
            h.y = to_tf32(v.y); l.y = to_tf32(v.y - h.y);
            h.z = to_tf32(v.z); l.z = to_tf32(v.z - h.z);
            h.w = to_tf32(v.w); l.w = to_tf32(v.w - h.w);
            *(float4*)&Bs_hi[bk][bn4 + 4 * i] = h;
            *(float4*)&Bs_lo[bk][bn4 + 4 * i] = l;
        }
        __syncthreads();

        // --- issue global loads for tile kt+1; they complete under the MMAs
        if (kt + 1 < NT) {
            const float* ga = Ag + (kt + 1) * 32;
            const float* gb = Bg + (long)(kt + 1) * BgK;
#pragma unroll
            for (int i = 0; i < 4; i++) {
                ra[i] = *(const float4*)(ga + 4 * i);
                rb[i] = *(const float4*)(gb + 4 * i);
            }
        }

        // --- MMA over tile kt (identical to R13 inner loop)
#pragma unroll
        for (int ks = 0; ks < 4; ks++) {
            const int kb = ks * 8;
            unsigned ah[4][4], al[4][4], bh[4][2], bl[4][2];
#pragma unroll
            for (int mt = 0; mt < 4; mt++) {
                int mr = wm + mt * 16 + g;
                ah[mt][0] = __float_as_uint(As_hi[mr    ][kb + t4    ]);
                ah[mt][1] = __float_as_uint(As_hi[mr + 8][kb + t4    ]);
                ah[mt][2] = __float_as_uint(As_hi[mr    ][kb + t4 + 4]);
                ah[mt][3] = __float_as_uint(As_hi[mr + 8][kb + t4 + 4]);
                al[mt][0] = __float_as_uint(As_lo[mr    ][kb + t4    ]);
                al[mt][1] = __float_as_uint(As_lo[mr + 8][kb + t4    ]);
                al[mt][2] = __float_as_uint(As_lo[mr    ][kb + t4 + 4]);
                al[mt][3] = __float_as_uint(As_lo[mr + 8][kb + t4 + 4]);
            }
#pragma unroll
            for (int nt = 0; nt < 4; nt++) {
                int nc = wn + nt * 8 + g;
                bh[nt][0] = __float_as_uint(Bs_hi[kb + t4    ][nc]);
                bh[nt][1] = __float_as_uint(Bs_hi[kb + t4 + 4][nc]);
                bl[nt][0] = __float_as_uint(Bs_lo[kb + t4    ][nc]);
                bl[nt][1] = __float_as_uint(Bs_lo[kb + t4 + 4][nc]);
            }
#pragma unroll
            for (int mt = 0; mt < 4; mt++)
#pragma unroll
                for (int nt = 0; nt < 4; nt++) {
                    mma_tf32(acc[mt][nt], al[mt], bh[nt]);  // lo*hi
                    mma_tf32(acc[mt][nt], ah[mt], bl[nt]);  // hi*lo
                    mma_tf32(acc[mt][nt], ah[mt], bh[nt]);  // hi*hi
                }
        }
        __syncthreads();
    }

    // epilogue: c0,c1 at (g, 2*t4[,+1]); c2,c3 at (g+8, ...)
#pragma unroll
    for (int mt = 0; mt < 4; mt++) {
#pragma unroll
        for (int nt = 0; nt < 4; nt++) {
            long col = n0 + wn + nt * 8 + 2 * t4;
            float bb0 = bias ? bias[col] : 0.f;
            float bb1 = bias ? bias[col + 1] : 0.f;
#pragma unroll
            for (int half = 0; half < 2; half++) {
                long row = m0 + wm + mt * 16 + g + half * 8;
                float v0 = acc[mt][nt][half * 2 + 0] + bb0;
                float v1 = acc[mt][nt][half * 2 + 1] + bb1;
                if (gelu_flag) {
                    v0 = 0.5f * v0 * (1.f + erff(v0 * 0.70710678118654752f));
                    v1 = 0.5f * v1 * (1.f + erff(v1 * 0.70710678118654752f));
                }
                *(float2*)&C[row * N + col] = make_float2(v0, v1);
            }
        }
    }
}

// =====================================================================
// Generic tiled FFMA SGEMM (small conv GEMMs with odd shapes)
// =====================================================================
__global__ __launch_bounds__(256)
void sgemm_kernel(const float* __restrict__ A, const float* __restrict__ B,
                  const float* __restrict__ bias, float* __restrict__ C,
                  int M, int N, int K,
                  long sA, long sB, long sC, int gelu_flag)
{
    A += (long)blockIdx.z * sA;
    B += (long)blockIdx.z * sB;
    C += (long)blockIdx.z * sC;

    __shared__ float As[8][128];
    __shared__ float Bs[8][128];

    const int tid = threadIdx.x;
    const int ty  = tid >> 4;
    const int tx  = tid & 15;
    const int m0  = blockIdx.y * 128;
    const int n0  = blockIdx.x * 128;

    float acc[8][8];
#pragma unroll
    for (int i = 0; i < 8; i++)
#pragma unroll
        for (int j = 0; j < 8; j++) acc[i][j] = 0.f;

    for (int k0 = 0; k0 < K; k0 += 8) {
#pragma unroll
        for (int u = 0; u < 4; u++) {
            int l = tid * 4 + u;
            int m = l >> 3, k = l & 7;
            int gm = m0 + m, gk = k0 + k;
            As[k][m] = (gm < M && gk < K) ? A[(long)gm * K + gk] : 0.f;
        }
#pragma unroll
        for (int u = 0; u < 4; u++) {
            int l = tid * 4 + u;
            int k = l >> 7, n = l & 127;
            int gk = k0 + k, gn = n0 + n;
            Bs[k][n] = (gk < K && gn < N) ? B[(long)gk * N + gn] : 0.f;
        }
        __syncthreads();
#pragma unroll
        for (int kk = 0; kk < 8; kk++) {
            float a[8], bb[8];
#pragma unroll
            for (int i = 0; i < 8; i++) a[i]  = As[kk][ty * 8 + i];
#pragma unroll
            for (int j = 0; j < 8; j++) bb[j] = Bs[kk][tx * 8 + j];
#pragma unroll
            for (int i = 0; i < 8; i++)
#pragma unroll
                for (int j = 0; j < 8; j++) acc[i][j] += a[i] * bb[j];
        }
        __syncthreads();
    }

#pragma unroll
    for (int i = 0; i < 8; i++) {
        int gm = m0 + ty * 8 + i;
        if (gm >= M) continue;
#pragma unroll
        for (int j = 0; j < 8; j++) {
            int gn = n0 + tx * 8 + j;
            if (gn >= N) continue;
            float v = acc[i][j] + (bias ? bias[gn] : 0.f);
            if (gelu_flag) v = 0.5f * v * (1.f + erff(v * 0.70710678118654752f));
            C[(long)gm * N + gn] = v;
        }
    }
}

// =====================================================================
// Embedding sum
// =====================================================================
__global__ void embed_kernel(const int* __restrict__ ids, const int* __restrict__ tti,
                             const float* __restrict__ tok, const float* __restrict__ pos,
                             const float* __restrict__ typ)
{
    int t = blockIdx.x;
    int s = t & (Sn - 1);
    int id = ids[t], tp = tti[t];
    const float* tr = tok + (long)id * Hn;
    const float* pr = pos + (long)s * Hn;
    const float* yr = typ + (long)tp * Hn;
    for (int i = threadIdx.x; i < Hn; i += blockDim.x)
        g_h[(long)t * Hn + i] = tr[i] + pr[i] + yr[i];
}

// =====================================================================
// LayerNorm: o = LN(a + d) * g + be   (d may be null; o may alias a)
// =====================================================================
__global__ __launch_bounds__(256)
void ln_kernel(const float* __restrict__ a, const float* __restrict__ d,
               const float* __restrict__ g, const float* __restrict__ be,
               float* __restrict__ o)
{
    long t = blockIdx.x;
    const float* ar = a + t * Hn;
    const float* dr = d ? d + t * Hn : nullptr;
    int tid = threadIdx.x;
    float vals[3];
    float sum = 0.f;
#pragma unroll
    for (int j = 0; j < 3; j++) {
        int i = tid + j * 256;
        float v = ar[i] + (dr ? dr[i] : 0.f);
        vals[j] = v; sum += v;
    }
    __shared__ float sh[8];
#pragma unroll
    for (int off = 16; off; off >>= 1) sum += __shfl_xor_sync(0xffffffffu, sum, off);
    if ((tid & 31) == 0) sh[tid >> 5] = sum;
    __syncthreads();
    float tot = 0.f;
#pragma unroll
    for (int w = 0; w < 8; w++) tot += sh[w];
    float mean = tot * (1.f / Hn);
    __syncthreads();
    float sq = 0.f;
#pragma unroll
    for (int j = 0; j < 3; j++) { float c = vals[j] - mean; sq += c * c; }
#pragma unroll
    for (int off = 16; off; off >>= 1) sq += __shfl_xor_sync(0xffffffffu, sq, off);
    if ((tid & 31) == 0) sh[tid >> 5] = sq;
    __syncthreads();
    float vtot = 0.f;
#pragma unroll
    for (int w = 0; w < 8; w++) vtot += sh[w];
    float inv = rsqrtf(vtot * (1.f / Hn) + 1e-12f);
#pragma unroll
    for (int j = 0; j < 3; j++) {
        int i = tid + j * 256;
        o[t * Hn + i] = (vals[j] - mean) * inv * g[i] + be[i];
    }
}

// =====================================================================
// Fused attention per (head, batch)
// =====================================================================
#define ATT_SMEM ((2*64*128 + 128*129) * 4)
__global__ __launch_bounds__(256)
void attention_kernel(const int* __restrict__ am)
{
    int h = blockIdx.x, b = blockIdx.y;
    extern __shared__ float sm[];
    float* Qt = sm;
    float* Kt = sm + 64 * 128;
    float* Ss = sm + 2 * 64 * 128;
    float* Vs = Qt;

    int tid = threadIdx.x;
    const float* base = g_qkv + (long)b * Sn * 3 * Hn + h * DHn;

    for (int idx = tid; idx < Sn * DHn; idx += 256) {
        int s = idx >> 6, d = idx & 63;
        Qt[d * 128 + s] = base[(long)s * 3 * Hn + d];
        Kt[d * 128 + s] = base[(long)s * 3 * Hn + Hn + d];
    }
    __syncthreads();

    int ty = tid >> 4, tx = tid & 15;
    float acc[8][8];
#pragma unroll
    for (int i = 0; i < 8; i++)
#pragma unroll
        for (int j = 0; j < 8; j++) acc[i][j] = 0.f;

    for (int d = 0; d < 64; d++) {
        float a[8], bb[8];
#pragma unroll
        for (int i = 0; i < 8; i++) a[i]  = Qt[d * 128 + ty * 8 + i];
#pragma unroll
        for (int j = 0; j < 8; j++) bb[j] = Kt[d * 128 + tx * 8 + j];
#pragma unroll
        for (int i = 0; i < 8; i++)
#pragma unroll
            for (int j = 0; j < 8; j++) acc[i][j] += a[i] * bb[j];
    }
#pragma unroll
    for (int j = 0; j < 8; j++) {
        int key = tx * 8 + j;
        float bias = (am[b * Sn + key] > 0) ? 0.f : -1e9f;
#pragma unroll
        for (int i = 0; i < 8; i++)
            Ss[(ty * 8 + i) * 129 + key] = acc[i][j] * 0.125f + bias;
    }
    __syncthreads();

    int wid = tid >> 5, lane = tid & 31;
    for (int r = wid; r < 128; r += 8) {
        float mx = -1e30f;
        for (int c = lane; c < 128; c += 32) mx = fmaxf(mx, Ss[r * 129 + c]);
#pragma unroll
        for (int off = 16; off; off >>= 1) mx = fmaxf(mx, __shfl_xor_sync(0xffffffffu, mx, off));
        float sumv = 0.f;
        for (int c = lane; c < 128; c += 32) {
            float e = expf(Ss[r * 129 + c] - mx);
            Ss[r * 129 + c] = e; sumv += e;
        }
#pragma unroll
        for (int off = 16; off; off >>= 1) sumv += __shfl_xor_sync(0xffffffffu, sumv, off);
        float inv = 1.f / sumv;
        for (int c = lane; c < 128; c += 32) Ss[r * 129 + c] *= inv;
    }
    __syncthreads();

    for (int idx = tid; idx < Sn * DHn; idx += 256) {
        int s = idx >> 6, d = idx & 63;
        Vs[s * 64 + d] = base[(long)s * 3 * Hn + 2 * Hn + d];
    }
    __syncthreads();

    float acc2[8][4];
#pragma unroll
    for (int i = 0; i < 8; i++)
#pragma unroll
        for (int j = 0; j < 4; j++) acc2[i][j] = 0.f;

    for (int key = 0; key < 128; key++) {
        float a[8], bb[4];
#pragma unroll
        for (int i = 0; i < 8; i++) a[i]  = Ss[(ty * 8 + i) * 129 + key];
#pragma unroll
        for (int j = 0; j < 4; j++) bb[j] = Vs[key * 64 + tx * 4 + j];
#pragma unroll
        for (int i = 0; i < 8; i++)
#pragma unroll
            for (int j = 0; j < 4; j++) acc2[i][j] += a[i] * bb[j];
    }
    float* outp = g_att + (long)b * Sn * Hn + h * DHn;
#pragma unroll
    for (int i = 0; i < 8; i++)
#pragma unroll
        for (int j = 0; j < 4; j++)
            outp[(long)(ty * 8 + i) * Hn + tx * 4 + j] = acc2[i][j];
}

// =====================================================================
// im2col patches
// =====================================================================
__global__ void patch1_kernel()
{
    long e = (long)blockIdx.x * 256 + threadIdx.x;
    long total = (long)Bn * K1 * C1OUT;
    if (e >= total) return;
    int t  = (int)(e % C1OUT);
    long r = e / C1OUT;
    int ik = (int)(r % K1);
    int b  = (int)(r / K1);
    int i  = ik / 5, k = ik % 5;
    g_p1[e] = g_h[((long)(b * Sn + 1 + i)) * Hn + 2 * t + k];
}

__global__ void patch2_kernel(const float* __restrict__ c1b)
{
    long e = (long)blockIdx.x * 256 + threadIdx.x;
    long total = (long)Bn * K2 * C2OUT;
    if (e >= total) return;
    int t  = (int)(e % C2OUT);
    long r = e / C2OUT;
    int ik = (int)(r % K2);
    int b  = (int)(r / K2);
    int i  = ik / 3, k = ik % 3;
    g_p2[e] = g_c1[((long)b * SPn + i) * C1OUT + 2 * t + 2 * k] + c1b[i];
}

// =====================================================================
// logits
// =====================================================================
__global__ void logits_kernel(const float* __restrict__ c2b,
                              const float* __restrict__ linw,
                              const float* __restrict__ linb)
{
    int e = blockIdx.x * 256 + threadIdx.x;
    if (e >= Bn * SPn * Tn) return;
    int tag = e % Tn;
    int r   = e / Tn;
    int ch  = r % SPn;
    int b   = r / SPn;
    const float* crow = g_c2 + ((long)b * SPn + ch) * C2OUT;
    float cb = c2b[ch];
    float acc = linb[tag];
    for (int t = 0; t < C2OUT; t++)
        acc += (crow[t] + cb) * linw[t * Tn + tag];
    g_lg[e] = acc;
}

// =====================================================================
// CRF
// =====================================================================
__global__ void crf_kernel(const int* __restrict__ am, const int* __restrict__ y,
                           const float* __restrict__ startv, const float* __restrict__ endv,
                           const float* __restrict__ trans, float* __restrict__ dout)
{
    int b = blockIdx.x;
    int j = threadIdx.x;
    const float* em = g_lg + (long)b * SPn * Tn;

    __shared__ float s[Tn], sv[Tn];
    __shared__ int   hist[SPn - 1][Tn];
    __shared__ float tr[Tn * Tn];
    __shared__ int   msk[SPn];
    __shared__ int   pathsh[SPn];

    for (int i = j; i < Tn * Tn; i += 32) tr[i] = trans[i];
    for (int t = j; t < SPn; t += 32) msk[t] = am[b * Sn + 1 + t];
    __syncthreads();

    if (j < Tn) { s[j] = startv[j] + em[j]; sv[j] = s[j]; }
    __syncthreads();

    for (int t = 1; t < SPn; t++) {
        float nsj = 0.f, nvj = 0.f; int bi = 0;
        if (j < Tn) {
            float mx = -1e30f;
#pragma unroll
            for (int i = 0; i < Tn; i++) mx = fmaxf(mx, s[i] + tr[i * Tn + j]);
            float sm = 0.f;
#pragma unroll
            for (int i = 0; i < Tn; i++) sm += expf(s[i] + tr[i * Tn + j] - mx);
            nsj = mx + logf(sm) + em[t * Tn + j];

            float best = -1e30f;
#pragma unroll
            for (int i = 0; i < Tn; i++) {
                float c = sv[i] + tr[i * Tn + j];
                if (c > best) { best = c; bi = i; }
            }
            nvj = best + em[t * Tn + j];
        }
        __syncthreads();
        if (j < Tn) {
            if (msk[t]) { s[j] = nsj; sv[j] = nvj; hist[t - 1][j] = bi; }
            else        { hist[t - 1][j] = j; }
        }
        __syncthreads();
    }

    if (j == 0) {
        float mx = -1e30f;
#pragma unroll
        for (int jj = 0; jj < Tn; jj++) mx = fmaxf(mx, s[jj] + endv[jj]);
        float sm = 0.f;
#pragma unroll
        for (int jj = 0; jj < Tn; jj++) sm += expf(s[jj] + endv[jj] - mx);
        float norm = mx + logf(sm);

        float best = -1e30f; int tag = 0;
#pragma unroll
        for (int jj = 0; jj < Tn; jj++) {
            float c = sv[jj] + endv[jj];
            if (c > best) { best = c; tag = jj; }
        }
        for (int t = SPn - 2; t >= 0; t--) {
            pathsh[t + 1] = tag;
            tag = hist[t][tag];
        }
        pathsh[0] = tag;

        const int* tg = y + b * SPn;
        float sc = startv[tg[0]] + em[tg[0]];
        int cnt = 0;
        for (int t = 0; t < SPn; t++) cnt += msk[t] ? 1 : 0;
        for (int t = 1; t < SPn; t++)
            if (msk[t]) sc += tr[tg[t - 1] * Tn + tg[t]] + em[t * Tn + tg[t]];
        sc += endv[tg[cnt - 1]];
        g_llhb[b] = sc - norm;
    }
    __syncthreads();
    for (int t = j; t < SPn; t += 32)
        dout[1 + b * SPn + t] = (float)pathsh[t];
}

__global__ void finalize_kernel(float* __restrict__ dout)
{
    if (threadIdx.x == 0) {
        float sm = 0.f;
        for (int b = 0; b < Bn; b++) sm += g_llhb[b];
        dout[0] = sm / (float)Bn;
    }
}

// =====================================================================
// host orchestration
// =====================================================================
extern "C" void kernel_launch(void* const* d_in, const int* in_sizes, int n_in,
                              void* d_out, int out_size)
{
    const int*   input_ids = (const int*)  d_in[0];
    const int*   am        = (const int*)  d_in[1];
    const int*   tti       = (const int*)  d_in[2];
    const int*   y_true    = (const int*)  d_in[3];
    const float* tok  = (const float*)d_in[4];
    const float* pos  = (const float*)d_in[5];
    const float* typ  = (const float*)d_in[6];
    const float* eg   = (const float*)d_in[7];
    const float* ebv  = (const float*)d_in[8];
    const float* Wqkv = (const float*)d_in[9];
    const float* bqkv = (const float*)d_in[10];
    const float* Wo   = (const float*)d_in[11];
    const float* bo   = (const float*)d_in[12];
    const float* l1g  = (const float*)d_in[13];
    const float* l1b  = (const float*)d_in[14];
    const float* W1   = (const float*)d_in[15];
    const float* bf1  = (const float*)d_in[16];
    const float* W2   = (const float*)d_in[17];
    const float* bf2  = (const float*)d_in[18];
    const float* l2g  = (const float*)d_in[19];
    const float* l2b  = (const float*)d_in[20];
    const float* c1w  = (const float*)d_in[21];
    const float* c1b  = (const float*)d_in[22];
    const float* c2w  = (const float*)d_in[23];
    const float* c2b  = (const float*)d_in[24];
    const float* linw = (const float*)d_in[25];
    const float* linb = (const float*)d_in[26];
    const float* crs  = (const float*)d_in[27];
    const float* cre  = (const float*)d_in[28];
    const float* crt  = (const float*)d_in[29];
    float* dout = (float*)d_out;

    float *p_h, *p_qkv, *p_att, *p_ff, *p_p1, *p_c1, *p_p2, *p_c2;
    cudaGetSymbolAddress((void**)&p_h,   g_h);
    cudaGetSymbolAddress((void**)&p_qkv, g_qkv);
    cudaGetSymbolAddress((void**)&p_att, g_att);
    cudaGetSymbolAddress((void**)&p_ff,  g_ff);
    cudaGetSymbolAddress((void**)&p_p1,  g_p1);
    cudaGetSymbolAddress((void**)&p_c1,  g_c1);
    cudaGetSymbolAddress((void**)&p_p2,  g_p2);
    cudaGetSymbolAddress((void**)&p_c2,  g_c2);

    cudaFuncSetAttribute(attention_kernel,
                         cudaFuncAttributeMaxDynamicSharedMemorySize, ATT_SMEM);
    cudaFuncSetAttribute(tf32x3_gemm_kernel,
                         cudaFuncAttributeMaxDynamicSharedMemorySize, GEMM_SMEM);

    embed_kernel<<<MTOK, 256>>>(input_ids, tti, tok, pos, typ);
    ln_kernel<<<MTOK, 256>>>(p_h, nullptr, eg, ebv, p_h);

    for (int l = 0; l < Ln; l++) {
        tf32x3_gemm_kernel<<<dim3(18, 32), 256, GEMM_SMEM>>>(
            p_h, Wqkv + (long)l * Hn * 3 * Hn, bqkv + (long)l * 3 * Hn, p_qkv,
            MTOK, 3 * Hn, Hn, 0);
        attention_kernel<<<dim3(NHn, Bn), 256, ATT_SMEM>>>(am);
        tf32x3_gemm_kernel<<<dim3(6, 32), 256, GEMM_SMEM>>>(
            p_att, Wo + (long)l * Hn * Hn, bo + (long)l * Hn, p_qkv,
            MTOK, Hn, Hn, 0);
        ln_kernel<<<MTOK, 256>>>(p_h, p_qkv, l1g + (long)l * Hn, l1b + (long)l * Hn, p_h);
        tf32x3_gemm_kernel<<<dim3(24, 32), 256, GEMM_SMEM>>>(
            p_h, W1 + (long)l * Hn * FFn, bf1 + (long)l * FFn, p_ff,
            MTOK, FFn, Hn, 1);
        tf32x3_gemm_kernel<<<dim3(6, 32), 256, GEMM_SMEM>>>(
            p_ff, W2 + (long)l * FFn * Hn, bf2 + (long)l * Hn, p_qkv,
            MTOK, Hn, FFn, 0);
        ln_kernel<<<MTOK, 256>>>(p_h, p_qkv, l2g + (long)l * Hn, l2b + (long)l * Hn, p_h);
    }

    {
        long t1 = (long)Bn * K1 * C1OUT;
        patch1_kernel<<<(unsigned)((t1 + 255) / 256), 256>>>();
        sgemm_kernel<<<dim3(3, 1, Bn), 256>>>(c1w, p_p1, nullptr, p_c1,
                                              SPn, C1OUT, K1,
                                              0, (long)K1 * C1OUT, (long)SPn * C1OUT, 0);
        long t2 = (long)Bn * K2 * C2OUT;
        patch2_kernel<<<(unsigned)((t2 + 255) / 256), 256>>>(c1b);
        sgemm_kernel<<<dim3(2, 1, Bn), 256>>>(c2w, p_p2, nullptr, p_c2,
                                              SPn, C2OUT, K2,
                                              0, (long)K2 * C2OUT, (long)SPn * C2OUT, 0);
        int t3 = Bn * SPn * Tn;
        logits_kernel<<<(t3 + 255) / 256, 256>>>(c2b, linw, linb);
    }

    crf_kernel<<<Bn, 32>>>(am, y_true, crs, cre, crt, dout);
    finalize_kernel<<<1, 32>>>(dout);
}

// round 17
// speedup vs baseline: 1.1461x; 1.0011x over previous
#include <cuda_runtime.h>
#include <math.h>

#define Bn   32
#define Sn   128
#define Hn   768
#define Ln   12
#define NHn  12
#define DHn  64
#define FFn  3072
#define Tn   9
#define SPn  127
#define MTOK (Bn*Sn)          // 4096 tokens

// conv geometry
#define C1OUT 382
#define C2OUT 189
#define K1    635             // 127*5
#define K2    381             // 127*3

// ---------------- scratch (device globals; no allocations) ----------------
__device__ float g_h   [MTOK * Hn];
__device__ float g_qkv [MTOK * 3 * Hn];
__device__ float g_att [MTOK * Hn];
__device__ float g_ff  [MTOK * FFn];
__device__ float g_p1  [Bn * K1 * C1OUT];
__device__ float g_c1  [Bn * SPn * C1OUT];
__device__ float g_p2  [Bn * K2 * C2OUT];
__device__ float g_c2  [Bn * SPn * C2OUT];
__device__ float g_lg  [Bn * SPn * Tn];
__device__ float g_llhb[Bn];

// =====================================================================
// TF32x3 tensor-core GEMM (split-precision, ~fp32 accuracy) with
// register-staged double buffering of global loads.
//   C = A(MxK) @ B(KxN) + bias(N), optional exact GELU.
// REQUIRES: M,N % 128 == 0, K % 32 == 0.
// hi/lo tf32 split done ONCE at STS time (amortized over fragment reuse);
// product = Alo*Bhi + Ahi*Blo + Ahi*Bhi.
// 128x128 block tile, KTILE=32, 8 warps (2m x 4n) of 64x32 warp tiles.
// Mainloop: STS(tile t) -> sync -> LDG regs(tile t+1) -> MMA(tile t) -> sync.
// LDG latency drains under the MMA phase.
// Conflict-free fragment LDS:
//   As[m][36]  -> bank(4g+t4) lane-unique for (g,t4) A-frag pattern
//   Bs[k][136] -> bank(8t4+g) lane-unique for (t4,g) B-frag pattern
// Dyn smem: (2*128*36 + 2*32*136)*4 = 71680 B (single k-tile, hi+lo).
// =====================================================================
#define GEMM_SMEM ((2*128*36 + 2*32*136) * 4)

__device__ __forceinline__ float to_tf32(float x) {
    float r;
    asm("cvt.rna.tf32.f32 %0, %1;" : "=f"(r) : "f"(x));
    return r;
}

__device__ __forceinline__ void mma_tf32(float* c, const unsigned* a, const unsigned* b) {
    asm volatile(
        "mma.sync.aligned.m16n8k8.row.col.f32.tf32.tf32.f32 "
        "{%0,%1,%2,%3}, {%4,%5,%6,%7}, {%8,%9}, {%0,%1,%2,%3};"
        : "+f"(c[0]), "+f"(c[1]), "+f"(c[2]), "+f"(c[3])
        : "r"(a[0]), "r"(a[1]), "r"(a[2]), "r"(a[3]), "r"(b[0]), "r"(b[1]));
}

__global__ __launch_bounds__(256)
void tf32x3_gemm_kernel(const float* __restrict__ A, const float* __restrict__ B,
                        const float* __restrict__ bias, float* __restrict__ C,
                        int M, int N, int K, int gelu_flag)
{
    extern __shared__ float dyn[];
    float (*As_hi)[36]  = (float(*)[36]) dyn;
    float (*As_lo)[36]  = (float(*)[36])(dyn + 128 * 36);
    float (*Bs_hi)[136] = (float(*)[136])(dyn + 2 * 128 * 36);
    float (*Bs_lo)[136] = (float(*)[136])(dyn + 2 * 128 * 36 + 32 * 136);

    const int tid  = threadIdx.x;
    const int wid  = tid >> 5;
    const int lane = tid & 31;
    const int g    = lane >> 2;         // 0..7
    const int t4   = lane & 3;          // 0..3
    const int wm   = (wid >> 2) * 64;   // warp m offset (0 / 64)
    const int wn   = (wid & 3) * 32;    // warp n offset (0/32/64/96)
    const long m0  = (long)blockIdx.y * 128;
    const long n0  = (long)blockIdx.x * 128;

    // loader indices
    const int lm  = tid >> 1;           // A row 0..127
    const int lkh = (tid & 1) * 16;     // A k half (0/16)
    const int bk  = tid >> 3;           // B k row 0..31
    const int bn4 = (tid & 7) * 16;     // B n chunk (16 floats)

    const float* Ag = A + (m0 + lm) * K + lkh;
    const float* Bg = B + (long)bk * N + n0 + bn4;
    const long  BgK = (long)32 * N;     // per-ktile B advance

    float acc[4][4][4];
#pragma unroll
    for (int mt = 0; mt < 4; mt++)
#pragma unroll
        for (int nt = 0; nt < 4; nt++)
#pragma unroll
            for (int r = 0; r < 4; r++) acc[mt][nt][r] = 0.f;

    const int NT = K >> 5;

    // prefetch tile 0 into registers
    float4 ra[4], rb[4];
#pragma unroll
    for (int i = 0; i < 4; i++) {
        ra[i] = *(const float4*)(Ag + 4 * i);
        rb[i] = *(const float4*)(Bg + 4 * i);
    }

    for (int kt = 0; kt < NT; kt++) {
        // --- split staged registers hi/lo and store to smem (tile kt)
#pragma unroll
        for (int i = 0; i < 4; i++) {
            float4 v = ra[i], h, l;
            h.x = to_tf32(v.x); l.x = to_tf32(v.x - h.x);
            h.y = to_tf32(v.y); l.y = to_tf32(v.y - h.y);
            h.z = to_tf32(v.z); l.z = to_tf32(v.z - h.z);
            h.w = to_tf32(v.w); l.w = to_tf32(v.w - h.w);
            *(float4*)&As_hi[lm][lkh + 4 * i] = h;
            *(float4*)&As_lo[lm][lkh + 4 * i] = l;
            v = rb[i];
            h.x = to_tf32(v.x); l.x = to_tf32(v.x - h.x);
            h.y = to_tf32(v.y); l.y = to_tf32(v.y - h.y);
            h.z = to_tf32(v.z); l.z = to_tf32(v.z - h.z);
            h.w = to_tf32(v.w); l.w = to_tf32(v.w - h.w);
            *(float4*)&Bs_hi[bk][bn4 + 4 * i] = h;
            *(float4*)&Bs_lo[bk][bn4 + 4 * i] = l;
        }
        __syncthreads();

        // --- issue global loads for tile kt+1; they complete under the MMAs
        if (kt + 1 < NT) {
            const float* ga = Ag + (kt + 1) * 32;
            const float* gb = Bg + (long)(kt + 1) * BgK;
#pragma unroll
            for (int i = 0; i < 4; i++) {
                ra[i] = *(const float4*)(ga + 4 * i);
                rb[i] = *(const float4*)(gb + 4 * i);
            }
        }

        // --- MMA over tile kt (identical to R13 inner loop)
#pragma unroll
        for (int ks = 0; ks < 4; ks++) {
            const int kb = ks * 8;
            unsigned ah[4][4], al[4][4], bh[4][2], bl[4][2];
#pragma unroll
            for (int mt = 0; mt < 4; mt++) {
                int mr = wm + mt * 16 + g;
                ah[mt][0] = __float_as_uint(As_hi[mr    ][kb + t4    ]);
                ah[mt][1] = __float_as_uint(As_hi[mr + 8][kb + t4    ]);
                ah[mt][2] = __float_as_uint(As_hi[mr    ][kb + t4 + 4]);
                ah[mt][3] = __float_as_uint(As_hi[mr + 8][kb + t4 + 4]);
                al[mt][0] = __float_as_uint(As_lo[mr    ][kb + t4    ]);
                al[mt][1] = __float_as_uint(As_lo[mr + 8][kb + t4    ]);
                al[mt][2] = __float_as_uint(As_lo[mr    ][kb + t4 + 4]);
                al[mt][3] = __float_as_uint(As_lo[mr + 8][kb + t4 + 4]);
            }
#pragma unroll
            for (int nt = 0; nt < 4; nt++) {
                int nc = wn + nt * 8 + g;
                bh[nt][0] = __float_as_uint(Bs_hi[kb + t4    ][nc]);
                bh[nt][1] = __float_as_uint(Bs_hi[kb + t4 + 4][nc]);
                bl[nt][0] = __float_as_uint(Bs_lo[kb + t4    ][nc]);
                bl[nt][1] = __float_as_uint(Bs_lo[kb + t4 + 4][nc]);
            }
#pragma unroll
            for (int mt = 0; mt < 4; mt++)
#pragma unroll
                for (int nt = 0; nt < 4; nt++) {
                    mma_tf32(acc[mt][nt], al[mt], bh[nt]);  // lo*hi
                    mma_tf32(acc[mt][nt], ah[mt], bl[nt]);  // hi*lo
                    mma_tf32(acc[mt][nt], ah[mt], bh[nt]);  // hi*hi
                }
        }
        __syncthreads();
    }

    // epilogue: c0,c1 at (g, 2*t4[,+1]); c2,c3 at (g+8, ...)
#pragma unroll
    for (int mt = 0; mt < 4; mt++) {
#pragma unroll
        for (int nt = 0; nt < 4; nt++) {
            long col = n0 + wn + nt * 8 + 2 * t4;
            float bb0 = bias ? bias[col] : 0.f;
            float bb1 = bias ? bias[col + 1] : 0.f;
#pragma unroll
            for (int half = 0; half < 2; half++) {
                long row = m0 + wm + mt * 16 + g + half * 8;
                float v0 = acc[mt][nt][half * 2 + 0] + bb0;
                float v1 = acc[mt][nt][half * 2 + 1] + bb1;
                if (gelu_flag) {
                    v0 = 0.5f * v0 * (1.f + erff(v0 * 0.70710678118654752f));
                    v1 = 0.5f * v1 * (1.f + erff(v1 * 0.70710678118654752f));
                }
                *(float2*)&C[row * N + col] = make_float2(v0, v1);
            }
        }
    }
}

// =====================================================================
// Generic tiled FFMA SGEMM (small conv GEMMs with odd shapes)
// =====================================================================
__global__ __launch_bounds__(256)
void sgemm_kernel(const float* __restrict__ A, const float* __restrict__ B,
                  const float* __restrict__ bias, float* __restrict__ C,
                  int M, int N, int K,
                  long sA, long sB, long sC, int gelu_flag)
{
    A += (long)blockIdx.z * sA;
    B += (long)blockIdx.z * sB;
    C += (long)blockIdx.z * sC;

    __shared__ float As[8][128];
    __shared__ float Bs[8][128];

    const int tid = threadIdx.x;
    const int ty  = tid >> 4;
    const int tx  = tid & 15;
    const int m0  = blockIdx.y * 128;
    const int n0  = blockIdx.x * 128;

    float acc[8][8];
#pragma unroll
    for (int i = 0; i < 8; i++)
#pragma unroll
        for (int j = 0; j < 8; j++) acc[i][j] = 0.f;

    for (int k0 = 0; k0 < K; k0 += 8) {
#pragma unroll
        for (int u = 0; u < 4; u++) {
            int l = tid * 4 + u;
            int m = l >> 3, k = l & 7;
            int gm = m0 + m, gk = k0 + k;
            As[k][m] = (gm < M && gk < K) ? A[(long)gm * K + gk] : 0.f;
        }
#pragma unroll
        for (int u = 0; u < 4; u++) {
            int l = tid * 4 + u;
            int k = l >> 7, n = l & 127;
            int gk = k0 + k, gn = n0 + n;
            Bs[k][n] = (gk < K && gn < N) ? B[(long)gk * N + gn] : 0.f;
        }
        __syncthreads();
#pragma unroll
        for (int kk = 0; kk < 8; kk++) {
            float a[8], bb[8];
#pragma unroll
            for (int i = 0; i < 8; i++) a[i]  = As[kk][ty * 8 + i];
#pragma unroll
            for (int j = 0; j < 8; j++) bb[j] = Bs[kk][tx * 8 + j];
#pragma unroll
            for (int i = 0; i < 8; i++)
#pragma unroll
                for (int j = 0; j < 8; j++) acc[i][j] += a[i] * bb[j];
        }
        __syncthreads();
    }

#pragma unroll
    for (int i = 0; i < 8; i++) {
        int gm = m0 + ty * 8 + i;
        if (gm >= M) continue;
#pragma unroll
        for (int j = 0; j < 8; j++) {
            int gn = n0 + tx * 8 + j;
            if (gn >= N) continue;
            float v = acc[i][j] + (bias ? bias[gn] : 0.f);
            if (gelu_flag) v = 0.5f * v * (1.f + erff(v * 0.70710678118654752f));
            C[(long)gm * N + gn] = v;
        }
    }
}

// =====================================================================
// Embedding sum
// =====================================================================
__global__ void embed_kernel(const int* __restrict__ ids, const int* __restrict__ tti,
                             const float* __restrict__ tok, const float* __restrict__ pos,
                             const float* __restrict__ typ)
{
    int t = blockIdx.x;
    int s = t & (Sn - 1);
    int id = ids[t], tp = tti[t];
    const float* tr = tok + (long)id * Hn;
    const float* pr = pos + (long)s * Hn;
    const float* yr = typ + (long)tp * Hn;
    for (int i = threadIdx.x; i < Hn; i += blockDim.x)
        g_h[(long)t * Hn + i] = tr[i] + pr[i] + yr[i];
}

// =====================================================================
// LayerNorm: o = LN(a + d) * g + be   (d may be null; o may alias a)
// =====================================================================
__global__ __launch_bounds__(256)
void ln_kernel(const float* __restrict__ a, const float* __restrict__ d,
               const float* __restrict__ g, const float* __restrict__ be,
               float* __restrict__ o)
{
    long t = blockIdx.x;
    const float* ar = a + t * Hn;
    const float* dr = d ? d + t * Hn : nullptr;
    int tid = threadIdx.x;
    float vals[3];
    float sum = 0.f;
#pragma unroll
    for (int j = 0; j < 3; j++) {
        int i = tid + j * 256;
        float v = ar[i] + (dr ? dr[i] : 0.f);
        vals[j] = v; sum += v;
    }
    __shared__ float sh[8];
#pragma unroll
    for (int off = 16; off; off >>= 1) sum += __shfl_xor_sync(0xffffffffu, sum, off);
    if ((tid & 31) == 0) sh[tid >> 5] = sum;
    __syncthreads();
    float tot = 0.f;
#pragma unroll
    for (int w = 0; w < 8; w++) tot += sh[w];
    float mean = tot * (1.f / Hn);
    __syncthreads();
    float sq = 0.f;
#pragma unroll
    for (int j = 0; j < 3; j++) { float c = vals[j] - mean; sq += c * c; }
#pragma unroll
    for (int off = 16; off; off >>= 1) sq += __shfl_xor_sync(0xffffffffu, sq, off);
    if ((tid & 31) == 0) sh[tid >> 5] = sq;
    __syncthreads();
    float vtot = 0.f;
#pragma unroll
    for (int w = 0; w < 8; w++) vtot += sh[w];
    float inv = rsqrtf(vtot * (1.f / Hn) + 1e-12f);
#pragma unroll
    for (int j = 0; j < 3; j++) {
        int i = tid + j * 256;
        o[t * Hn + i] = (vals[j] - mean) * inv * g[i] + be[i];
    }
}

// =====================================================================
// Fused attention per (head, batch)
// =====================================================================
#define ATT_SMEM ((2*64*128 + 128*129) * 4)
__global__ __launch_bounds__(256)
void attention_kernel(const int* __restrict__ am)
{
    int h = blockIdx.x, b = blockIdx.y;
    extern __shared__ float sm[];
    float* Qt = sm;
    float* Kt = sm + 64 * 128;
    float* Ss = sm + 2 * 64 * 128;
    float* Vs = Qt;

    int tid = threadIdx.x;
    const float* base = g_qkv + (long)b * Sn * 3 * Hn + h * DHn;

    for (int idx = tid; idx < Sn * DHn; idx += 256) {
        int s = idx >> 6, d = idx & 63;
        Qt[d * 128 + s] = base[(long)s * 3 * Hn + d];
        Kt[d * 128 + s] = base[(long)s * 3 * Hn + Hn + d];
    }
    __syncthreads();

    int ty = tid >> 4, tx = tid & 15;
    float acc[8][8];
#pragma unroll
    for (int i = 0; i < 8; i++)
#pragma unroll
        for (int j = 0; j < 8; j++) acc[i][j] = 0.f;

    for (int d = 0; d < 64; d++) {
        float a[8], bb[8];
#pragma unroll
        for (int i = 0; i < 8; i++) a[i]  = Qt[d * 128 + ty * 8 + i];
#pragma unroll
        for (int j = 0; j < 8; j++) bb[j] = Kt[d * 128 + tx * 8 + j];
#pragma unroll
        for (int i = 0; i < 8; i++)
#pragma unroll
            for (int j = 0; j < 8; j++) acc[i][j] += a[i] * bb[j];
    }
#pragma unroll
    for (int j = 0; j < 8; j++) {
        int key = tx * 8 + j;
        float bias = (am[b * Sn + key] > 0) ? 0.f : -1e9f;
#pragma unroll
        for (int i = 0; i < 8; i++)
            Ss[(ty * 8 + i) * 129 + key] = acc[i][j] * 0.125f + bias;
    }
    __syncthreads();

    int wid = tid >> 5, lane = tid & 31;
    for (int r = wid; r < 128; r += 8) {
        float mx = -1e30f;
        for (int c = lane; c < 128; c += 32) mx = fmaxf(mx, Ss[r * 129 + c]);
#pragma unroll
        for (int off = 16; off; off >>= 1) mx = fmaxf(mx, __shfl_xor_sync(0xffffffffu, mx, off));
        float sumv = 0.f;
        for (int c = lane; c < 128; c += 32) {
            float e = expf(Ss[r * 129 + c] - mx);
            Ss[r * 129 + c] = e; sumv += e;
        }
#pragma unroll
        for (int off = 16; off; off >>= 1) sumv += __shfl_xor_sync(0xffffffffu, sumv, off);
        float inv = 1.f / sumv;
        for (int c = lane; c < 128; c += 32) Ss[r * 129 + c] *= inv;
    }
    __syncthreads();

    for (int idx = tid; idx < Sn * DHn; idx += 256) {
        int s = idx >> 6, d = idx & 63;
        Vs[s * 64 + d] = base[(long)s * 3 * Hn + 2 * Hn + d];
    }
    __syncthreads();

    float acc2[8][4];
#pragma unroll
    for (int i = 0; i < 8; i++)
#pragma unroll
        for (int j = 0; j < 4; j++) acc2[i][j] = 0.f;

    for (int key = 0; key < 128; key++) {
        float a[8], bb[4];
#pragma unroll
        for (int i = 0; i < 8; i++) a[i]  = Ss[(ty * 8 + i) * 129 + key];
#pragma unroll
        for (int j = 0; j < 4; j++) bb[j] = Vs[key * 64 + tx * 4 + j];
#pragma unroll
        for (int i = 0; i < 8; i++)
#pragma unroll
            for (int j = 0; j < 4; j++) acc2[i][j] += a[i] * bb[j];
    }
    float* outp = g_att + (long)b * Sn * Hn + h * DHn;
#pragma unroll
    for (int i = 0; i < 8; i++)
#pragma unroll
        for (int j = 0; j < 4; j++)
            outp[(long)(ty * 8 + i) * Hn + tx * 4 + j] = acc2[i][j];
}

// =====================================================================
// im2col patches
// =====================================================================
__global__ void patch1_kernel()
{
    long e = (long)blockIdx.x * 256 + threadIdx.x;
    long total = (long)Bn * K1 * C1OUT;
    if (e >= total) return;
    int t  = (int)(e % C1OUT);
    long r = e / C1OUT;
    int ik = (int)(r % K1);
    int b  = (int)(r / K1);
    int i  = ik / 5, k = ik % 5;
    g_p1[e] = g_h[((long)(b * Sn + 1 + i)) * Hn + 2 * t + k];
}

__global__ void patch2_kernel(const float* __restrict__ c1b)
{
    long e = (long)blockIdx.x * 256 + threadIdx.x;
    long total = (long)Bn * K2 * C2OUT;
    if (e >= total) return;
    int t  = (int)(e % C2OUT);
    long r = e / C2OUT;
    int ik = (int)(r % K2);
    int b  = (int)(r / K2);
    int i  = ik / 3, k = ik % 3;
    g_p2[e] = g_c1[((long)b * SPn + i) * C1OUT + 2 * t + 2 * k] + c1b[i];
}

// =====================================================================
// logits
// =====================================================================
__global__ void logits_kernel(const float* __restrict__ c2b,
                              const float* __restrict__ linw,
                              const float* __restrict__ linb)
{
    int e = blockIdx.x * 256 + threadIdx.x;
    if (e >= Bn * SPn * Tn) return;
    int tag = e % Tn;
    int r   = e / Tn;
    int ch  = r % SPn;
    int b   = r / SPn;
    const float* crow = g_c2 + ((long)b * SPn + ch) * C2OUT;
    float cb = c2b[ch];
    float acc = linb[tag];
    for (int t = 0; t < C2OUT; t++)
        acc += (crow[t] + cb) * linw[t * Tn + tag];
    g_lg[e] = acc;
}

// =====================================================================
// CRF
// =====================================================================
__global__ void crf_kernel(const int* __restrict__ am, const int* __restrict__ y,
                           const float* __restrict__ startv, const float* __restrict__ endv,
                           const float* __restrict__ trans, float* __restrict__ dout)
{
    int b = blockIdx.x;
    int j = threadIdx.x;
    const float* em = g_lg + (long)b * SPn * Tn;

    __shared__ float s[Tn], sv[Tn];
    __shared__ int   hist[SPn - 1][Tn];
    __shared__ float tr[Tn * Tn];
    __shared__ int   msk[SPn];
    __shared__ int   pathsh[SPn];

    for (int i = j; i < Tn * Tn; i += 32) tr[i] = trans[i];
    for (int t = j; t < SPn; t += 32) msk[t] = am[b * Sn + 1 + t];
    __syncthreads();

    if (j < Tn) { s[j] = startv[j] + em[j]; sv[j] = s[j]; }
    __syncthreads();

    for (int t = 1; t < SPn; t++) {
        float nsj = 0.f, nvj = 0.f; int bi = 0;
        if (j < Tn) {
            float mx = -1e30f;
#pragma unroll
            for (int i = 0; i < Tn; i++) mx = fmaxf(mx, s[i] + tr[i * Tn + j]);
            float sm = 0.f;
#pragma unroll
            for (int i = 0; i < Tn; i++) sm += expf(s[i] + tr[i * Tn + j] - mx);
            nsj = mx + logf(sm) + em[t * Tn + j];

            float best = -1e30f;
#pragma unroll
            for (int i = 0; i < Tn; i++) {
                float c = sv[i] + tr[i * Tn + j];
                if (c > best) { best = c; bi = i; }
            }
            nvj = best + em[t * Tn + j];
        }
        __syncthreads();
        if (j < Tn) {
            if (msk[t]) { s[j] = nsj; sv[j] = nvj; hist[t - 1][j] = bi; }
            else        { hist[t - 1][j] = j; }
        }
        __syncthreads();
    }

    if (j == 0) {
        float mx = -1e30f;
#pragma unroll
        for (int jj = 0; jj < Tn; jj++) mx = fmaxf(mx, s[jj] + endv[jj]);
        float sm = 0.f;
#pragma unroll
        for (int jj = 0; jj < Tn; jj++) sm += expf(s[jj] + endv[jj] - mx);
        float norm = mx + logf(sm);

        float best = -1e30f; int tag = 0;
#pragma unroll
        for (int jj = 0; jj < Tn; jj++) {
            float c = sv[jj] + endv[jj];
            if (c > best) { best = c; tag = jj; }
        }
        for (int t = SPn - 2; t >= 0; t--) {
            pathsh[t + 1] = tag;
            tag = hist[t][tag];
        }
        pathsh[0] = tag;

        const int* tg = y + b * SPn;
        float sc = startv[tg[0]] + em[tg[0]];
        int cnt = 0;
        for (int t = 0; t < SPn; t++) cnt += msk[t] ? 1 : 0;
        for (int t = 1; t < SPn; t++)
            if (msk[t]) sc += tr[tg[t - 1] * Tn + tg[t]] + em[t * Tn + tg[t]];
        sc += endv[tg[cnt - 1]];
        g_llhb[b] = sc - norm;
    }
    __syncthreads();
    for (int t = j; t < SPn; t += 32)
        dout[1 + b * SPn + t] = (float)pathsh[t];
}

__global__ void finalize_kernel(float* __restrict__ dout)
{
    if (threadIdx.x == 0) {
        float sm = 0.f;
        for (int b = 0; b < Bn; b++) sm += g_llhb[b];
        dout[0] = sm / (float)Bn;
    }
}

// =====================================================================
// host orchestration
// =====================================================================
extern "C" void kernel_launch(void* const* d_in, const int* in_sizes, int n_in,
                              void* d_out, int out_size)
{
    const int*   input_ids = (const int*)  d_in[0];
    const int*   am        = (const int*)  d_in[1];
    const int*   tti       = (const int*)  d_in[2];
    const int*   y_true    = (const int*)  d_in[3];
    const float* tok  = (const float*)d_in[4];
    const float* pos  = (const float*)d_in[5];
    const float* typ  = (const float*)d_in[6];
    const float* eg   = (const float*)d_in[7];
    const float* ebv  = (const float*)d_in[8];
    const float* Wqkv = (const float*)d_in[9];
    const float* bqkv = (const float*)d_in[10];
    const float* Wo   = (const float*)d_in[11];
    const float* bo   = (const float*)d_in[12];
    const float* l1g  = (const float*)d_in[13];
    const float* l1b  = (const float*)d_in[14];
    const float* W1   = (const float*)d_in[15];
    const float* bf1  = (const float*)d_in[16];
    const float* W2   = (const float*)d_in[17];
    const float* bf2  = (const float*)d_in[18];
    const float* l2g  = (const float*)d_in[19];
    const float* l2b  = (const float*)d_in[20];
    const float* c1w  = (const float*)d_in[21];
    const float* c1b  = (const float*)d_in[22];
    const float* c2w  = (const float*)d_in[23];
    const float* c2b  = (const float*)d_in[24];
    const float* linw = (const float*)d_in[25];
    const float* linb = (const float*)d_in[26];
    const float* crs  = (const float*)d_in[27];
    const float* cre  = (const float*)d_in[28];
    const float* crt  = (const float*)d_in[29];
    float* dout = (float*)d_out;

    float *p_h, *p_qkv, *p_att, *p_ff, *p_p1, *p_c1, *p_p2, *p_c2;
    cudaGetSymbolAddress((void**)&p_h,   g_h);
    cudaGetSymbolAddress((void**)&p_qkv, g_qkv);
    cudaGetSymbolAddress((void**)&p_att, g_att);
    cudaGetSymbolAddress((void**)&p_ff,  g_ff);
    cudaGetSymbolAddress((void**)&p_p1,  g_p1);
    cudaGetSymbolAddress((void**)&p_c1,  g_c1);
    cudaGetSymbolAddress((void**)&p_p2,  g_p2);
    cudaGetSymbolAddress((void**)&p_c2,  g_c2);

    cudaFuncSetAttribute(attention_kernel,
                         cudaFuncAttributeMaxDynamicSharedMemorySize, ATT_SMEM);
    cudaFuncSetAttribute(tf32x3_gemm_kernel,
                         cudaFuncAttributeMaxDynamicSharedMemorySize, GEMM_SMEM);

    embed_kernel<<<MTOK, 256>>>(input_ids, tti, tok, pos, typ);
    ln_kernel<<<MTOK, 256>>>(p_h, nullptr, eg, ebv, p_h);

    for (int l = 0; l < Ln; l++) {
        tf32x3_gemm_kernel<<<dim3(18, 32), 256, GEMM_SMEM>>>(
            p_h, Wqkv + (long)l * Hn * 3 * Hn, bqkv + (long)l * 3 * Hn, p_qkv,
            MTOK, 3 * Hn, Hn, 0);
        attention_kernel<<<dim3(NHn, Bn), 256, ATT_SMEM>>>(am);
        tf32x3_gemm_kernel<<<dim3(6, 32), 256, GEMM_SMEM>>>(
            p_att, Wo + (long)l * Hn * Hn, bo + (long)l * Hn, p_qkv,
            MTOK, Hn, Hn, 0);
        ln_kernel<<<MTOK, 256>>>(p_h, p_qkv, l1g + (long)l * Hn, l1b + (long)l * Hn, p_h);
        tf32x3_gemm_kernel<<<dim3(24, 32), 256, GEMM_SMEM>>>(
            p_h, W1 + (long)l * Hn * FFn, bf1 + (long)l * FFn, p_ff,
            MTOK, FFn, Hn, 1);
        tf32x3_gemm_kernel<<<dim3(6, 32), 256, GEMM_SMEM>>>(
            p_ff, W2 + (long)l * FFn * Hn, bf2 + (long)l * Hn, p_qkv,
            MTOK, Hn, FFn, 0);
        ln_kernel<<<MTOK, 256>>>(p_h, p_qkv, l2g + (long)l * Hn, l2b + (long)l * Hn, p_h);
    }

    {
        long t1 = (long)Bn * K1 * C1OUT;
        patch1_kernel<<<(unsigned)((t1 + 255) / 256), 256>>>();
        sgemm_kernel<<<dim3(3, 1, Bn), 256>>>(c1w, p_p1, nullptr, p_c1,
                                              SPn, C1OUT, K1,
                                              0, (long)K1 * C1OUT, (long)SPn * C1OUT, 0);
        long t2 = (long)Bn * K2 * C2OUT;
        patch2_kernel<<<(unsigned)((t2 + 255) / 256), 256>>>(c1b);
        sgemm_kernel<<<dim3(2, 1, Bn), 256>>>(c2w, p_p2, nullptr, p_c2,
                                              SPn, C2OUT, K2,
                                              0, (long)K2 * C2OUT, (long)SPn * C2OUT, 0);
        int t3 = Bn * SPn * Tn;
        logits_kernel<<<(t3 + 255) / 256, 256>>>(c2b, linw, linb);
    }

    crf_kernel<<<Bn, 32>>>(am, y_true, crs, cre, crt, dout);
    finalize_kernel<<<1, 32>>>(dout);
}